// round 3
// baseline (speedup 1.0000x reference)
#include <cuda_runtime.h>
#include <cuda_bf16.h>

// Problem constants
#define Hd 256
#define Wd 256
#define HWn 65536
#define Bn 4
#define Dn 5
#define Cn 3
#define Sn 27

// Output layout in d_out (flattened tuple: res_i, out, samples)
#define RES_OFF  0L
#define OUT_OFF  (4L*3*3*HWn)               // 2359296
#define SAMP_OFF (OUT_OFF + 4L*3*HWn)       // 3145728

// Scratch (device globals; no runtime allocation allowed)
__device__ float g_f1[4L*64*HWn];    // f1 (64ch) ; reused for h2
__device__ float g_feat[4L*128*HWn]; // feature (128ch)
__device__ float g_off[4L*81*HWn];   // offsets (81ch)
__device__ float g_h1[4L*64*HWn];    // h1 (64ch)
__device__ float g_wt[4L*27*HWn];    // weights (27ch)

typedef unsigned long long ull;

// Packed fp32x2 helpers (Blackwell sm_103a packed-FMA path; ptxas never emits
// these from C++ — inline PTX only).
__device__ __forceinline__ ull pack2(float lo, float hi) {
    ull d;
    asm("mov.b64 %0, {%1, %2};" : "=l"(d) : "f"(lo), "f"(hi));
    return d;
}
__device__ __forceinline__ void fma2(ull& d, ull a, ull b) {
    asm("fma.rn.f32x2 %0, %1, %2, %0;" : "+l"(d) : "l"(a), "l"(b));
}
__device__ __forceinline__ float2 unpack2(ull v) {
    float2 f;
    asm("mov.b64 {%0, %1}, %2;" : "=f"(f.x), "=f"(f.y) : "l"(v));
    return f;
}

// ---------------------------------------------------------------------------
// Generic 3x3 SAME conv, stride 1, fp32 with packed f32x2 FMA.
// Input channels may come from up to 3 concatenated sources.
// Block: 256 threads, 32x32 output tile, 8 out-channels per block.
// Each thread: 4 vertical pixels x 8 out-channels; pixel pairs packed into
// 64-bit registers -> 144 FFMA2 per thread per input channel.
// ---------------------------------------------------------------------------
template<bool RELU>
__global__ void __launch_bounds__(256)
conv3x3_k(const float* __restrict__ s0, int c0, long bs0,
          const float* __restrict__ s1, int c1, long bs1,
          const float* __restrict__ s2, long bs2,
          const float* __restrict__ wgt, const float* __restrict__ bias,
          float* __restrict__ dst, int CIN, int COUT)
{
    const int tid = threadIdx.x;
    const int tx = tid & 31;
    const int ty = tid >> 5;            // 0..7
    const int tilex = blockIdx.x * 32;
    const int tiley = blockIdx.y * 32;
    const int nchunk = (COUT + 7) >> 3;
    const int b   = blockIdx.z / nchunk;
    const int ocb = (blockIdx.z % nchunk) * 8;

    __shared__ float tile[34 * 34];
    __shared__ float2 wsm2[72];          // weights duplicated into both halves

    ull acc[2][8];                       // [pixel-pair][oc]
#pragma unroll
    for (int p = 0; p < 2; p++)
#pragma unroll
        for (int o = 0; o < 8; o++) acc[p][o] = 0ull;

    for (int cin = 0; cin < CIN; ++cin) {
        const float* src;
        if (cin < c0)       src = s0 + b * bs0 + (long)cin * HWn;
        else if (cin < c1)  src = s1 + b * bs1 + (long)(cin - c0) * HWn;
        else                src = s2 + b * bs2 + (long)(cin - c1) * HWn;

        // stage weights (duplicated) for this input channel, 8 out-channels
        if (tid < 72) {
            int oc = ocb + tid / 9;
            float v = (oc < COUT) ? wgt[((long)oc * CIN + cin) * 9 + tid % 9] : 0.f;
            wsm2[tid] = make_float2(v, v);
        }
        // 34x34 halo tile (zero padding outside)
#pragma unroll 2
        for (int i = tid; i < 34 * 34; i += 256) {
            int r = i / 34, c = i - r * 34;
            int gh = tiley - 1 + r, gw = tilex - 1 + c;
            float v = 0.f;
            if ((unsigned)gh < (unsigned)Hd && (unsigned)gw < (unsigned)Wd)
                v = src[gh * Wd + gw];
            tile[i] = v;
        }
        __syncthreads();

        // 6 input rows x 3 columns needed for 4 output pixels
        float in_s[6][3];
#pragma unroll
        for (int i = 0; i < 6; i++)
#pragma unroll
            for (int j = 0; j < 3; j++)
                in_s[i][j] = tile[(ty * 4 + i) * 34 + tx + j];

        // pack vertical row pairs (r, r+1), r = 0..4
        ull pin[5][3];
#pragma unroll
        for (int r = 0; r < 5; r++)
#pragma unroll
            for (int j = 0; j < 3; j++)
                pin[r][j] = pack2(in_s[r][j], in_s[r + 1][j]);

#pragma unroll
        for (int o = 0; o < 8; o++) {
            ull w2[9];
#pragma unroll
            for (int k = 0; k < 9; k++)
                w2[k] = *reinterpret_cast<const ull*>(&wsm2[o * 9 + k]);
#pragma unroll
            for (int p2 = 0; p2 < 2; p2++)
#pragma unroll
                for (int kh = 0; kh < 3; kh++)
#pragma unroll
                    for (int kw = 0; kw < 3; kw++)
                        fma2(acc[p2][o], pin[2 * p2 + kh][kw], w2[kh * 3 + kw]);
        }
        __syncthreads();
    }

#pragma unroll
    for (int o = 0; o < 8; o++) {
        int oc = ocb + o;
        if (oc >= COUT) break;
        float bv = bias[oc];
        float* dp = dst + ((long)b * COUT + oc) * HWn + (tiley + ty * 4) * Wd + tilex + tx;
#pragma unroll
        for (int p2 = 0; p2 < 2; p2++) {
            float2 v = unpack2(acc[p2][o]);
            float v0 = v.x + bv, v1 = v.y + bv;
            if (RELU) { v0 = fmaxf(v0, 0.f); v1 = fmaxf(v1, 0.f); }
            dp[(2 * p2) * Wd]     = v0;
            dp[(2 * p2 + 1) * Wd] = v1;
        }
    }
}

// ---------------------------------------------------------------------------
// Trilinear deformable sampling: data[B,D,C,H,W], offsets[B,S*3,H,W]
// -> samples[B,S,C,H,W]
// ---------------------------------------------------------------------------
__global__ void trilerp_k(const float* __restrict__ data,
                          const float* __restrict__ off,
                          float* __restrict__ samp)
{
    long idx = blockIdx.x * 256L + threadIdx.x;      // over B*S*HW
    if (idx >= (long)Bn * Sn * HWn) return;
    int hw = (int)(idx % HWn);
    int s  = (int)((idx / HWn) % Sn);
    int b  = (int)(idx / ((long)Sn * HWn));
    int h = hw >> 8, w = hw & 255;

    int kd = s / 9 - 1;
    int kh = (s / 3) % 3 - 1;
    int kw = s % 3 - 1;

    const float* ob = off + ((long)b * (Sn * 3) + s * 3) * HWn + hw;
    float pd = 2.0f + (float)kd + ob[0];
    float ph = (float)h + (float)kh + ob[HWn];
    float pw = (float)w + (float)kw + ob[2L * HWn];
    pd = fminf(fmaxf(pd, 0.f), (float)(Dn - 1));
    ph = fminf(fmaxf(ph, 0.f), (float)(Hd - 1));
    pw = fminf(fmaxf(pw, 0.f), (float)(Wd - 1));

    float d0f = floorf(pd), h0f = floorf(ph), w0f = floorf(pw);
    float fd = pd - d0f, fh = ph - h0f, fw = pw - w0f;
    int d0 = (int)d0f, h0 = (int)h0f, w0 = (int)w0f;
    int d1 = min(d0 + 1, Dn - 1);
    int h1 = min(h0 + 1, Hd - 1);
    int w1 = min(w0 + 1, Wd - 1);

    float gd0 = 1.f - fd, gh0 = 1.f - fh, gw0 = 1.f - fw;
    float w000 = gd0 * gh0 * gw0, w001 = gd0 * gh0 * fw;
    float w010 = gd0 * fh  * gw0, w011 = gd0 * fh  * fw;
    float w100 = fd  * gh0 * gw0, w101 = fd  * gh0 * fw;
    float w110 = fd  * fh  * gw0, w111 = fd  * fh  * fw;

    long i00 = (long)h0 * Wd + w0;
    long i01 = (long)h0 * Wd + w1;
    long i10 = (long)h1 * Wd + w0;
    long i11 = (long)h1 * Wd + w1;

#pragma unroll
    for (int c = 0; c < Cn; c++) {
        const float* p0 = data + (((long)b * Dn + d0) * Cn + c) * HWn;
        const float* p1 = data + (((long)b * Dn + d1) * Cn + c) * HWn;
        float v = w000 * p0[i00] + w001 * p0[i01]
                + w010 * p0[i10] + w011 * p0[i11]
                + w100 * p1[i00] + w101 * p1[i01]
                + w110 * p1[i10] + w111 * p1[i11];
        samp[(((long)b * Sn + s) * Cn + c) * HWn + hw] = v;
    }
}

// ---------------------------------------------------------------------------
// Final kernel-prediction combine: res_i[B,3,3,H,W], out[B,3,H,W]
// ---------------------------------------------------------------------------
__global__ void combine_k(const float* __restrict__ samp,
                          const float* __restrict__ wts,
                          float* __restrict__ res_i,
                          float* __restrict__ outp)
{
    long idx = blockIdx.x * 256L + threadIdx.x;      // over B*HW
    if (idx >= (long)Bn * HWn) return;
    int hw = (int)(idx % HWn);
    int b  = (int)(idx / HWn);

    float wv[Sn];
#pragma unroll
    for (int s = 0; s < Sn; s++)
        wv[s] = wts[((long)b * Sn + s) * HWn + hw];

    float o[3] = {0.f, 0.f, 0.f};
#pragma unroll
    for (int g = 0; g < 3; g++) {
#pragma unroll
        for (int c = 0; c < 3; c++) {
            float r = 0.f;
#pragma unroll
            for (int k = 0; k < 9; k++) {
                int s = g * 9 + k;
                r += samp[(((long)b * Sn + s) * Cn + c) * HWn + hw] * wv[s];
            }
            r *= 3.0f;
            res_i[(((long)b * 3 + g) * 3 + c) * HWn + hw] = r;
            o[c] += r;
        }
    }
#pragma unroll
    for (int c = 0; c < 3; c++)
        outp[((long)b * 3 + c) * HWn + hw] = o[c] * (1.0f / 3.0f);
}

// ---------------------------------------------------------------------------
extern "C" void kernel_launch(void* const* d_in, const int* in_sizes, int n_in,
                              void* d_out, int out_size)
{
    const float* data   = (const float*)d_in[0];
    const float* enc_w1 = (const float*)d_in[1];
    const float* enc_b1 = (const float*)d_in[2];
    const float* enc_w2 = (const float*)d_in[3];
    const float* enc_b2 = (const float*)d_in[4];
    const float* off_w  = (const float*)d_in[5];
    const float* off_b  = (const float*)d_in[6];
    const float* wc_w1  = (const float*)d_in[7];
    const float* wc_b1  = (const float*)d_in[8];
    const float* wc_w2  = (const float*)d_in[9];
    const float* wc_b2  = (const float*)d_in[10];
    const float* wc_w3  = (const float*)d_in[11];
    const float* wc_b3  = (const float*)d_in[12];
    float* out = (float*)d_out;

    float* f1;   cudaGetSymbolAddress((void**)&f1,   g_f1);
    float* feat; cudaGetSymbolAddress((void**)&feat, g_feat);
    float* offs; cudaGetSymbolAddress((void**)&offs, g_off);
    float* h1;   cudaGetSymbolAddress((void**)&h1,   g_h1);
    float* wt;   cudaGetSymbolAddress((void**)&wt,   g_wt);
    float* h2 = f1;  // reuse: f1 dead after feature is computed

    float* res_i = out + RES_OFF;
    float* outp  = out + OUT_OFF;
    float* samp  = out + SAMP_OFF;

    dim3 blk(256);
    const int BIG = 1 << 30;

    // 1) f1 = relu(conv(data 15 -> 64))
    {
        dim3 grid(Wd / 32, Hd / 32, Bn * (64 / 8));
        conv3x3_k<true><<<grid, blk>>>(data, BIG, (long)15 * HWn,
                                       nullptr, BIG, 0, nullptr, 0,
                                       enc_w1, enc_b1, f1, 15, 64);
    }
    // 2) feature = relu(conv(f1 64 -> 128))
    {
        dim3 grid(Wd / 32, Hd / 32, Bn * (128 / 8));
        conv3x3_k<true><<<grid, blk>>>(f1, BIG, (long)64 * HWn,
                                       nullptr, BIG, 0, nullptr, 0,
                                       enc_w2, enc_b2, feat, 64, 128);
    }
    // 3) offsets = conv(feature 128 -> 81)
    {
        dim3 grid(Wd / 32, Hd / 32, Bn * ((81 + 7) / 8));
        conv3x3_k<false><<<grid, blk>>>(feat, BIG, (long)128 * HWn,
                                        nullptr, BIG, 0, nullptr, 0,
                                        off_w, off_b, offs, 128, 81);
    }
    // 4) samples = trilinear(data, offsets)  -> d_out samples slice
    {
        long n = (long)Bn * Sn * HWn;
        trilerp_k<<<(unsigned)((n + 255) / 256), blk>>>(data, offs, samp);
    }
    // 5) h1 = relu(conv(concat[data(15), feature(128), samples(81)] -> 64))
    {
        dim3 grid(Wd / 32, Hd / 32, Bn * (64 / 8));
        conv3x3_k<true><<<grid, blk>>>(data, 15, (long)15 * HWn,
                                       feat, 143, (long)128 * HWn,
                                       samp, (long)81 * HWn,
                                       wc_w1, wc_b1, h1, 224, 64);
    }
    // 6) h2 = relu(conv(h1 64 -> 64))
    {
        dim3 grid(Wd / 32, Hd / 32, Bn * (64 / 8));
        conv3x3_k<true><<<grid, blk>>>(h1, BIG, (long)64 * HWn,
                                       nullptr, BIG, 0, nullptr, 0,
                                       wc_w2, wc_b2, h2, 64, 64);
    }
    // 7) weights = conv(h2 64 -> 27)
    {
        dim3 grid(Wd / 32, Hd / 32, Bn * ((27 + 7) / 8));
        conv3x3_k<false><<<grid, blk>>>(h2, BIG, (long)64 * HWn,
                                        nullptr, BIG, 0, nullptr, 0,
                                        wc_w3, wc_b3, wt, 64, 27);
    }
    // 8) res_i + out
    {
        long n = (long)Bn * HWn;
        combine_k<<<(unsigned)((n + 255) / 256), blk>>>(samp, wt, res_i, outp);
    }
}

// round 5
// speedup vs baseline: 3.2926x; 3.2926x over previous
#include <cuda_runtime.h>
#include <cuda_bf16.h>

#define Hd 256
#define Wd 256
#define HWn 65536
#define Bn 4
#define Dn 5
#define Cn 3
#define Sn 27

#define RES_OFF  0L
#define OUT_OFF  (4L*3*3*HWn)
#define SAMP_OFF (OUT_OFF + 4L*3*HWn)

typedef unsigned short u16;
typedef unsigned int u32;

// ---------------- bf16 hi/lo scratch planes ----------------
__device__ u16 g_data_h[4L*15*HWn],  g_data_l[4L*15*HWn];
__device__ u16 g_f1_h[4L*64*HWn],    g_f1_l[4L*64*HWn];
__device__ u16 g_feat_h[4L*128*HWn], g_feat_l[4L*128*HWn];
__device__ u16 g_samp_h[4L*81*HWn],  g_samp_l[4L*81*HWn];
__device__ u16 g_h1_h[4L*64*HWn],    g_h1_l[4L*64*HWn];
__device__ u16 g_h2_h[4L*64*HWn],    g_h2_l[4L*64*HWn];
__device__ float g_off[4L*81*HWn];
__device__ float g_wt[4L*27*HWn];
__device__ u16 g_bh[6L*131072], g_bl[6L*131072];   // packed weights per conv

__device__ __forceinline__ u16 bf16_hi(float v) {
    __nv_bfloat16 h = __float2bfloat16(v);
    return *reinterpret_cast<u16*>(&h);
}
__device__ __forceinline__ float bf16_f(u16 b) {
    __nv_bfloat16 h = *reinterpret_cast<__nv_bfloat16*>(&b);
    return __bfloat162float(h);
}

// ---------------------------------------------------------------------------
// split fp32 -> bf16 hi/lo planes
// ---------------------------------------------------------------------------
__global__ void split_k(const float* __restrict__ src, u16* __restrict__ dh,
                        u16* __restrict__ dl, long n)
{
    long i = blockIdx.x * 256L + threadIdx.x;
    if (i >= n) return;
    float v = src[i];
    u16 h = bf16_hi(v);
    dh[i] = h;
    dl[i] = bf16_hi(v - bf16_f(h));
}

// ---------------------------------------------------------------------------
// pack conv weights [COUT][K=CIN*9] fp32 -> B[Npad][Kpad] bf16 hi/lo, zero pad
// ---------------------------------------------------------------------------
__global__ void packw_k(const float* __restrict__ w, u16* __restrict__ bh,
                        u16* __restrict__ bl, int COUT, int K, int Kpad, int Npad)
{
    long e = blockIdx.x * 256L + threadIdx.x;
    if (e >= (long)Npad * Kpad) return;
    int n = (int)(e / Kpad), k = (int)(e % Kpad);
    float v = (n < COUT && k < K) ? w[(long)n * K + k] : 0.f;
    u16 h = bf16_hi(v);
    bh[e] = h;
    bl[e] = bf16_hi(v - bf16_f(h));
}

// ---------------------------------------------------------------------------
// mma.sync m16n8k16 bf16 (HMMA tensor pipe; valid at compute_103 base target)
// ---------------------------------------------------------------------------
__device__ __forceinline__ void mma16816(float d[4], const u32 a[4], u32 b0, u32 b1)
{
    asm volatile(
        "mma.sync.aligned.m16n8k16.row.col.f32.bf16.bf16.f32 "
        "{%0,%1,%2,%3}, {%4,%5,%6,%7}, {%8,%9}, {%0,%1,%2,%3};"
        : "+f"(d[0]), "+f"(d[1]), "+f"(d[2]), "+f"(d[3])
        : "r"(a[0]), "r"(a[1]), "r"(a[2]), "r"(a[3]), "r"(b0), "r"(b1));
}

// A fragment (m16k16) from transposed SMEM tile At[k][m], pitch 136 u16.
// PTX mapping: a0={A[g][k0+2t],A[g][k0+2t+1]}, a1=rows g+8, a2=cols +8, a3=both.
// With At (col-major A): element A[m][k] = At[k][m].
__device__ __forceinline__ void ldAfrag(u32 a[4], const u16* At, int k0, int m, int t)
{
    const u16* r0 = At + (k0 + t * 2) * 136;   // k row pair base
    const u16* r1 = r0 + 136;
    const u16* r8 = r0 + 8 * 136;
    const u16* r9 = r8 + 136;
    a[0] = (u32)r0[m]     | ((u32)r1[m]     << 16);
    a[1] = (u32)r0[m + 8] | ((u32)r1[m + 8] << 16);
    a[2] = (u32)r8[m]     | ((u32)r9[m]     << 16);
    a[3] = (u32)r8[m + 8] | ((u32)r9[m + 8] << 16);
}

// ---------------------------------------------------------------------------
// Implicit-GEMM 3x3 SAME conv via mma.sync.
// Block: 256 thr (8 warps). Tile: M=128 pixels (half image row) x N=NT*8.
// K accumulated in chunks of 64. A im2col transposed [k][m] (pitch 272B),
// B weights [n][k] (pitch 144B). hi/lo bf16 split, 3 terms.
// ---------------------------------------------------------------------------
template<int NT>
__global__ void __launch_bounds__(256)
convM_k(const u16* __restrict__ s0h, const u16* __restrict__ s0l, int c0,
        const u16* __restrict__ s1h, const u16* __restrict__ s1l, int c1,
        const u16* __restrict__ s2h, const u16* __restrict__ s2l,
        const u16* __restrict__ bh, const u16* __restrict__ bl,
        const float* __restrict__ bias,
        u16* __restrict__ dsth, u16* __restrict__ dstl, float* __restrict__ dstf,
        int CIN, int COUT, int Kpad, int relu)
{
    extern __shared__ char sm[];
    u16* Ah = (u16*)sm;                         // 64 rows x 136 u16 (272B pitch)
    u16* Al = (u16*)(sm + 17408);
    u16* Bh = (u16*)(sm + 34816);               // Npad rows x 72 u16 (144B pitch)
    u16* Bl = (u16*)(sm + 34816 + NT * 8 * 144);
    const int Npad = NT * 8;

    const int tid = threadIdx.x;
    const int wid = tid >> 5;
    const int lane = tid & 31;
    const int g = lane >> 2;        // groupID
    const int t = lane & 3;         // threadID_in_group
    const int bidx = blockIdx.x;
    const int b = bidx >> 9;
    const int pix = (bidx & 511) * 128;
    const int h = pix >> 8;
    const int w0 = pix & 255;
    const int mb = wid * 16;        // warp's M base within tile

    float acc[NT][4];
#pragma unroll
    for (int i = 0; i < NT; i++)
#pragma unroll
        for (int j = 0; j < 4; j++) acc[i][j] = 0.f;

    const int K_eff = CIN * 9;
    const int c01 = c0 + c1;
    const int c2 = CIN - c01;
    const int nchunk = Kpad >> 6;

    for (int kc = 0; kc < nchunk; ++kc) {
        __syncthreads();   // previous chunk's fragment reads complete

        // ---- B tile: [n][64k], vectorized ----
        for (int e = tid; e < Npad * 8; e += 256) {
            int n = e >> 3, j = e & 7;
            long go = (long)n * Kpad + kc * 64 + j * 8;
            *(uint4*)(Bh + n * 72 + j * 8) = *(const uint4*)(bh + go);
            *(uint4*)(Bl + n * 72 + j * 8) = *(const uint4*)(bl + go);
        }
        // ---- A tile: im2col transposed; element (klocal, 8 m's) ----
        for (int e = tid; e < 1024; e += 256) {
            int kl = e >> 4;             // 0..63
            int mg = (e & 15) * 8;       // m group base
            int k = kc * 64 + kl;
            union { u16 s[8]; uint4 v; } uh, ul;
#pragma unroll
            for (int j = 0; j < 8; j++) { uh.s[j] = 0; ul.s[j] = 0; }
            if (k < K_eff) {
                int cin = k / 9;
                int tap = k - cin * 9;
                int hh = h + tap / 3 - 1;
                if ((unsigned)hh < 256u) {
                    const u16 *ph, *pl;
                    if (cin < c0)       { ph = s0h + ((long)b * c0 + cin) * HWn;
                                          pl = s0l + ((long)b * c0 + cin) * HWn; }
                    else if (cin < c01) { ph = s1h + ((long)b * c1 + cin - c0) * HWn;
                                          pl = s1l + ((long)b * c1 + cin - c0) * HWn; }
                    else                { int cc = cin - c01;
                                          ph = s2h + ((long)b * c2 + cc) * HWn;
                                          pl = s2l + ((long)b * c2 + cc) * HWn; }
                    long rowo = (long)hh * 256;
                    int wwb = w0 + mg + (tap % 3) - 1;
#pragma unroll
                    for (int j = 0; j < 8; j++) {
                        int ww = wwb + j;
                        if ((unsigned)ww < 256u) {
                            uh.s[j] = ph[rowo + ww];
                            ul.s[j] = pl[rowo + ww];
                        }
                    }
                }
            }
            *(uint4*)(Ah + kl * 136 + mg) = uh.v;
            *(uint4*)(Al + kl * 136 + mg) = ul.v;
        }
        __syncthreads();

        // ---- MMA: 4 k-steps of 16 ----
#pragma unroll
        for (int ks = 0; ks < 4; ks++) {
            const int k0 = ks * 16;
            u32 ah[4], al[4];
            ldAfrag(ah, Ah, k0, mb + g, t);
            ldAfrag(al, Al, k0, mb + g, t);
#pragma unroll
            for (int nt = 0; nt < NT; nt++) {
                const u16* brh = Bh + (nt * 8 + g) * 72 + k0 + t * 2;
                const u16* brl = Bl + (nt * 8 + g) * 72 + k0 + t * 2;
                u32 bh0 = *(const u32*)(brh);
                u32 bh1 = *(const u32*)(brh + 8);
                u32 bl0 = *(const u32*)(brl);
                u32 bl1 = *(const u32*)(brl + 8);
                mma16816(acc[nt], ah, bh0, bh1);
                mma16816(acc[nt], al, bh0, bh1);
                mma16816(acc[nt], ah, bl0, bl1);
            }
        }
    }

    // ---- epilogue ----
#pragma unroll
    for (int nt = 0; nt < NT; nt++) {
        int n0 = nt * 8 + t * 2;
#pragma unroll
        for (int i = 0; i < 4; i++) {
            int n = n0 + (i & 1);
            if (n >= COUT) continue;
            int m = mb + g + ((i & 2) ? 8 : 0);
            float v = acc[nt][i] + bias[n];
            if (relu) v = fmaxf(v, 0.f);
            long o = ((long)b * COUT + n) * HWn + pix + m;
            if (dsth) {
                u16 hv = bf16_hi(v);
                dsth[o] = hv;
                dstl[o] = bf16_hi(v - bf16_f(hv));
            }
            if (dstf) dstf[o] = v;
        }
    }
}

// ---------------------------------------------------------------------------
// Trilinear deformable sampling; writes fp32 samples (d_out) + bf16 hi/lo.
// ---------------------------------------------------------------------------
__global__ void trilerp_k(const float* __restrict__ data,
                          const float* __restrict__ off,
                          float* __restrict__ samp,
                          u16* __restrict__ sh, u16* __restrict__ sl)
{
    long idx = blockIdx.x * 256L + threadIdx.x;
    if (idx >= (long)Bn * Sn * HWn) return;
    int hw = (int)(idx % HWn);
    int s  = (int)((idx / HWn) % Sn);
    int b  = (int)(idx / ((long)Sn * HWn));
    int h = hw >> 8, w = hw & 255;

    int kd = s / 9 - 1, kh = (s / 3) % 3 - 1, kw = s % 3 - 1;

    const float* ob = off + ((long)b * (Sn * 3) + s * 3) * HWn + hw;
    float pd = 2.0f + (float)kd + ob[0];
    float ph = (float)h + (float)kh + ob[HWn];
    float pw = (float)w + (float)kw + ob[2L * HWn];
    pd = fminf(fmaxf(pd, 0.f), (float)(Dn - 1));
    ph = fminf(fmaxf(ph, 0.f), (float)(Hd - 1));
    pw = fminf(fmaxf(pw, 0.f), (float)(Wd - 1));

    float d0f = floorf(pd), h0f = floorf(ph), w0f = floorf(pw);
    float fd = pd - d0f, fh = ph - h0f, fw = pw - w0f;
    int d0 = (int)d0f, h0 = (int)h0f, w0 = (int)w0f;
    int d1 = min(d0 + 1, Dn - 1), h1 = min(h0 + 1, Hd - 1), w1 = min(w0 + 1, Wd - 1);

    float gd0 = 1.f - fd, gh0 = 1.f - fh, gw0 = 1.f - fw;
    float w000 = gd0*gh0*gw0, w001 = gd0*gh0*fw, w010 = gd0*fh*gw0, w011 = gd0*fh*fw;
    float w100 = fd*gh0*gw0,  w101 = fd*gh0*fw,  w110 = fd*fh*gw0,  w111 = fd*fh*fw;

    long i00 = (long)h0 * Wd + w0, i01 = (long)h0 * Wd + w1;
    long i10 = (long)h1 * Wd + w0, i11 = (long)h1 * Wd + w1;

#pragma unroll
    for (int c = 0; c < Cn; c++) {
        const float* p0 = data + (((long)b * Dn + d0) * Cn + c) * HWn;
        const float* p1 = data + (((long)b * Dn + d1) * Cn + c) * HWn;
        float v = w000*p0[i00] + w001*p0[i01] + w010*p0[i10] + w011*p0[i11]
                + w100*p1[i00] + w101*p1[i01] + w110*p1[i10] + w111*p1[i11];
        long o = (((long)b * Sn + s) * Cn + c) * HWn + hw;
        samp[o] = v;
        u16 hv = bf16_hi(v);
        sh[o] = hv;
        sl[o] = bf16_hi(v - bf16_f(hv));
    }
}

// ---------------------------------------------------------------------------
__global__ void combine_k(const float* __restrict__ samp,
                          const float* __restrict__ wts,
                          float* __restrict__ res_i, float* __restrict__ outp)
{
    long idx = blockIdx.x * 256L + threadIdx.x;
    if (idx >= (long)Bn * HWn) return;
    int hw = (int)(idx % HWn);
    int b  = (int)(idx / HWn);

    float wv[Sn];
#pragma unroll
    for (int s = 0; s < Sn; s++) wv[s] = wts[((long)b * Sn + s) * HWn + hw];

    float o[3] = {0.f, 0.f, 0.f};
#pragma unroll
    for (int g = 0; g < 3; g++) {
#pragma unroll
        for (int c = 0; c < 3; c++) {
            float r = 0.f;
#pragma unroll
            for (int k = 0; k < 9; k++) {
                int s = g * 9 + k;
                r += samp[(((long)b * Sn + s) * Cn + c) * HWn + hw] * wv[s];
            }
            r *= 3.0f;
            res_i[(((long)b * 3 + g) * 3 + c) * HWn + hw] = r;
            o[c] += r;
        }
    }
#pragma unroll
    for (int c = 0; c < 3; c++)
        outp[((long)b * 3 + c) * HWn + hw] = o[c] * (1.0f / 3.0f);
}

// ---------------------------------------------------------------------------
extern "C" void kernel_launch(void* const* d_in, const int* in_sizes, int n_in,
                              void* d_out, int out_size)
{
    const float* data   = (const float*)d_in[0];
    const float* enc_w1 = (const float*)d_in[1];
    const float* enc_b1 = (const float*)d_in[2];
    const float* enc_w2 = (const float*)d_in[3];
    const float* enc_b2 = (const float*)d_in[4];
    const float* off_w  = (const float*)d_in[5];
    const float* off_b  = (const float*)d_in[6];
    const float* wc_w1  = (const float*)d_in[7];
    const float* wc_b1  = (const float*)d_in[8];
    const float* wc_w2  = (const float*)d_in[9];
    const float* wc_b2  = (const float*)d_in[10];
    const float* wc_w3  = (const float*)d_in[11];
    const float* wc_b3  = (const float*)d_in[12];
    float* out = (float*)d_out;

    u16 *dh, *dl, *f1h, *f1l, *fth, *ftl, *sph, *spl, *h1h, *h1l, *h2h, *h2l, *pbh, *pbl;
    float *offs, *wt;
    cudaGetSymbolAddress((void**)&dh,  g_data_h);  cudaGetSymbolAddress((void**)&dl,  g_data_l);
    cudaGetSymbolAddress((void**)&f1h, g_f1_h);    cudaGetSymbolAddress((void**)&f1l, g_f1_l);
    cudaGetSymbolAddress((void**)&fth, g_feat_h);  cudaGetSymbolAddress((void**)&ftl, g_feat_l);
    cudaGetSymbolAddress((void**)&sph, g_samp_h);  cudaGetSymbolAddress((void**)&spl, g_samp_l);
    cudaGetSymbolAddress((void**)&h1h, g_h1_h);    cudaGetSymbolAddress((void**)&h1l, g_h1_l);
    cudaGetSymbolAddress((void**)&h2h, g_h2_h);    cudaGetSymbolAddress((void**)&h2l, g_h2_l);
    cudaGetSymbolAddress((void**)&offs, g_off);    cudaGetSymbolAddress((void**)&wt,  g_wt);
    cudaGetSymbolAddress((void**)&pbh, g_bh);      cudaGetSymbolAddress((void**)&pbl, g_bl);

    float* res_i = out + RES_OFF;
    float* outp  = out + OUT_OFF;
    float* samp  = out + SAMP_OFF;

    // conv table: {w, b, CIN, COUT, Kpad, Npad}
    struct CV { const float* w; const float* bs; int CIN, COUT, Kpad, Npad; };
    CV cv[6] = {
        {enc_w1, enc_b1,  15,  64,  192,  64},
        {enc_w2, enc_b2,  64, 128,  576, 128},
        {off_w,  off_b,  128,  81, 1152,  96},
        {wc_w1,  wc_b1,  224,  64, 2048,  64},
        {wc_w2,  wc_b2,   64,  64,  576,  64},
        {wc_w3,  wc_b3,   64,  27,  576,  32},
    };

    // 0) split input to bf16 hi/lo
    {
        long n = 4L * 15 * HWn;
        split_k<<<(unsigned)((n + 255) / 256), 256>>>(data, dh, dl, n);
    }
    // pack weights
    for (int i = 0; i < 6; i++) {
        long n = (long)cv[i].Npad * cv[i].Kpad;
        packw_k<<<(unsigned)((n + 255) / 256), 256>>>(cv[i].w, pbh + i * 131072L,
                                                      pbl + i * 131072L,
                                                      cv[i].COUT, cv[i].CIN * 9,
                                                      cv[i].Kpad, cv[i].Npad);
    }

    // one-time max-dsm attributes (host-side, capture-safe)
    cudaFuncSetAttribute(convM_k<4>,  cudaFuncAttributeMaxDynamicSharedMemorySize, 34816 + 2*32*144);
    cudaFuncSetAttribute(convM_k<8>,  cudaFuncAttributeMaxDynamicSharedMemorySize, 34816 + 2*64*144);
    cudaFuncSetAttribute(convM_k<12>, cudaFuncAttributeMaxDynamicSharedMemorySize, 34816 + 2*96*144);
    cudaFuncSetAttribute(convM_k<16>, cudaFuncAttributeMaxDynamicSharedMemorySize, 34816 + 2*128*144);

    const unsigned GRID = 2048;

    auto launch = [&](int ci, const u16* a0h, const u16* a0l, int c0,
                      const u16* a1h, const u16* a1l, int c1,
                      const u16* a2h, const u16* a2l,
                      u16* oh, u16* ol, float* of, int relu) {
        const CV& c = cv[ci];
        size_t dsm = 34816 + 2 * (size_t)c.Npad * 144;
        const u16* wbh = pbh + ci * 131072L;
        const u16* wbl = pbl + ci * 131072L;
        switch (c.Npad / 8) {
        case 4:  convM_k<4><<<GRID, 256, dsm>>>(a0h, a0l, c0, a1h, a1l, c1, a2h, a2l,
                    wbh, wbl, c.bs, oh, ol, of, c.CIN, c.COUT, c.Kpad, relu); break;
        case 8:  convM_k<8><<<GRID, 256, dsm>>>(a0h, a0l, c0, a1h, a1l, c1, a2h, a2l,
                    wbh, wbl, c.bs, oh, ol, of, c.CIN, c.COUT, c.Kpad, relu); break;
        case 12: convM_k<12><<<GRID, 256, dsm>>>(a0h, a0l, c0, a1h, a1l, c1, a2h, a2l,
                    wbh, wbl, c.bs, oh, ol, of, c.CIN, c.COUT, c.Kpad, relu); break;
        default: convM_k<16><<<GRID, 256, dsm>>>(a0h, a0l, c0, a1h, a1l, c1, a2h, a2l,
                    wbh, wbl, c.bs, oh, ol, of, c.CIN, c.COUT, c.Kpad, relu); break;
        }
    };

    // 1) f1 = relu(conv(data 15->64))
    launch(0, dh, dl, 15, nullptr, nullptr, 0, nullptr, nullptr, f1h, f1l, nullptr, 1);
    // 2) feature = relu(conv(f1 64->128))
    launch(1, f1h, f1l, 64, nullptr, nullptr, 0, nullptr, nullptr, fth, ftl, nullptr, 1);
    // 3) offsets = conv(feature 128->81), fp32
    launch(2, fth, ftl, 128, nullptr, nullptr, 0, nullptr, nullptr, nullptr, nullptr, offs, 0);
    // 4) samples
    {
        long n = (long)Bn * Sn * HWn;
        trilerp_k<<<(unsigned)((n + 255) / 256), 256>>>(data, offs, samp, sph, spl);
    }
    // 5) h1 = relu(conv(concat(data15, feat128, samp81) 224->64))
    launch(3, dh, dl, 15, fth, ftl, 128, sph, spl, h1h, h1l, nullptr, 1);
    // 6) h2 = relu(conv(h1 64->64))
    launch(4, h1h, h1l, 64, nullptr, nullptr, 0, nullptr, nullptr, h2h, h2l, nullptr, 1);
    // 7) weights = conv(h2 64->27), fp32
    launch(5, h2h, h2l, 64, nullptr, nullptr, 0, nullptr, nullptr, nullptr, nullptr, wt, 0);
    // 8) combine
    {
        long n = (long)Bn * HWn;
        combine_k<<<(unsigned)((n + 255) / 256), 256>>>(samp, wt, res_i, outp);
    }
}